// round 1
// baseline (speedup 1.0000x reference)
#include <cuda_runtime.h>
#include <math.h>

typedef unsigned long long u64;

#define BB 8
#define SS 2048
#define DIN 128
#define DD 40
#define DP 20          // D/2 float2 pairs
#define NROWS (BB*SS)

// ---------- scratch (device globals: no allocation allowed) ----------
__device__ float g_x[NROWS*DD];
__device__ float g_q[NROWS*DD];
__device__ float g_k[NROWS*DD];
__device__ float g_v[NROWS*DD];
__device__ float g_bias[4096];

// ---------- f32x2 helpers (FFMA2 only reachable via PTX) ----------
__device__ __forceinline__ u64 pack2(float x, float y) {
    u64 r; asm("mov.b64 %0,{%1,%2};" : "=l"(r) : "f"(x), "f"(y)); return r;
}
__device__ __forceinline__ float2 unpack2(u64 a) {
    float x, y; asm("mov.b64 {%0,%1},%2;" : "=f"(x), "=f"(y) : "l"(a));
    return make_float2(x, y);
}
__device__ __forceinline__ u64 ffma2(u64 a, u64 b, u64 c) {
    u64 d; asm("fma.rn.f32x2 %0,%1,%2,%3;" : "=l"(d) : "l"(a), "l"(b), "l"(c)); return d;
}
__device__ __forceinline__ u64 fmul2(u64 a, u64 b) {
    u64 d; asm("mul.rn.f32x2 %0,%1,%2;" : "=l"(d) : "l"(a), "l"(b)); return d;
}
__device__ __forceinline__ u64 fadd2(u64 a, u64 b) {
    u64 d; asm("add.rn.f32x2 %0,%1,%2;" : "=l"(d) : "l"(a), "l"(b)); return d;
}

// ---------- kernel B: relative-position bias table ----------
// rel = k - q in [-2048, 2047], table index = rel + 2048.
// Matches jax: half-buckets=16, max_exact=8, denom = f32(np.log(16.0)),
// (log(a/8)/denom)*8 truncated to int32, clamp to 15.
__global__ void bias_kernel(const float* __restrict__ rel_bias) {
    int idx = blockIdx.x * blockDim.x + threadIdx.x;   // 0..4095
    if (idx >= 4096) return;
    int rel = idx - 2048;
    int bucket = (rel > 0) ? 16 : 0;
    int a = rel < 0 ? -rel : rel;
    if (a < 8) {
        bucket += a;
    } else {
        float v = (logf((float)a * 0.125f) / 2.7725887222397811f) * 8.0f;
        int large = 8 + (int)v;
        bucket += (large < 15) ? large : 15;
    }
    g_bias[idx] = rel_bias[bucket];
}

// ---------- kernel A: x = relu(embs@Wa+ba); h = rms(x,ln1); q/k/v = h@W ----------
// warp-per-row; lanes 0..19 each own a float2 pair of the 40 outputs.
__global__ __launch_bounds__(256) void kernelA(
    const float* __restrict__ embs, const float* __restrict__ Wa,
    const float* __restrict__ ba,   const float* __restrict__ ln1,
    const float* __restrict__ Wq,   const float* __restrict__ Wk,
    const float* __restrict__ Wv)
{
    __shared__ __align__(16) float Wa_s[DIN*DD];
    __shared__ __align__(16) float Wq_s[DD*DD], Wk_s[DD*DD], Wv_s[DD*DD];
    __shared__ __align__(16) float ba_s[DD], ln1_s[DD];
    __shared__ __align__(16) float e_s[8][DIN];
    __shared__ u64 h_s[8][DD];   // h duplicated pairs {h,h}

    int tid = threadIdx.x;
    for (int i = tid; i < DIN*DD; i += 256) Wa_s[i] = Wa[i];
    for (int i = tid; i < DD*DD; i += 256) { Wq_s[i] = Wq[i]; Wk_s[i] = Wk[i]; Wv_s[i] = Wv[i]; }
    if (tid < DD) { ba_s[tid] = ba[tid]; ln1_s[tid] = ln1[tid]; }
    __syncthreads();

    int w = tid >> 5, lane = tid & 31;
    const float2* Wa2 = (const float2*)Wa_s;
    const u64* wq2 = (const u64*)Wq_s;
    const u64* wk2 = (const u64*)Wk_s;
    const u64* wv2 = (const u64*)Wv_s;

    for (int r = 0; r < 8; r++) {
        int row = (blockIdx.x * 8 + w) * 8 + r;
        // coalesced load of the 128-float emb row into this warp's smem slot
        float4 ev = ((const float4*)(embs + (size_t)row * DIN))[lane];
        ((float4*)e_s[w])[lane] = ev;
        __syncwarp();

        float ax = 0.f, ay = 0.f;
        if (lane < DP) {
            ax = ba_s[2*lane]; ay = ba_s[2*lane+1];
            #pragma unroll 16
            for (int i = 0; i < DIN; i++) {
                float e = e_s[w][i];            // broadcast
                float2 wa = Wa2[i*DP + lane];   // conflict-free
                ax = fmaf(e, wa.x, ax);
                ay = fmaf(e, wa.y, ay);
            }
            ax = fmaxf(ax, 0.f); ay = fmaxf(ay, 0.f);
        }
        float ssq = (lane < DP) ? (ax*ax + ay*ay) : 0.f;
        #pragma unroll
        for (int o = 16; o > 0; o >>= 1) ssq += __shfl_xor_sync(0xffffffffu, ssq, o);
        float rinv = rsqrtf(ssq / 40.0f + 1e-6f);

        if (lane < DP) {
            float hx = ax * rinv * ln1_s[2*lane];
            float hy = ay * rinv * ln1_s[2*lane+1];
            *(float2*)(g_x + (size_t)row*DD + 2*lane) = make_float2(ax, ay);
            h_s[w][2*lane]   = pack2(hx, hx);
            h_s[w][2*lane+1] = pack2(hy, hy);
        }
        __syncwarp();

        if (lane < DP) {
            u64 aq = 0, ak = 0, av = 0;
            #pragma unroll 8
            for (int i = 0; i < DD; i++) {
                u64 h2 = h_s[w][i];
                aq = ffma2(h2, wq2[i*DP + lane], aq);
                ak = ffma2(h2, wk2[i*DP + lane], ak);
                av = ffma2(h2, wv2[i*DP + lane], av);
            }
            float2 fq = unpack2(aq), fk = unpack2(ak), fv = unpack2(av);
            *(float2*)(g_q + (size_t)row*DD + 2*lane) = fq;
            *(float2*)(g_k + (size_t)row*DD + 2*lane) = fk;
            *(float2*)(g_v + (size_t)row*DD + 2*lane) = fv;
        }
        __syncwarp();
    }
}

// ---------- kernel C: flash attention + full fused epilogue ----------
// grid (16,8): x = q-tile, y = batch. 128 threads, 1 query/thread.
#define TK 32
__global__ __launch_bounds__(128) void kernelC(
    const float* __restrict__ Wo, const float* __restrict__ ln2,
    const float* __restrict__ wi, const float* __restrict__ wo,
    const float* __restrict__ lnf, float* __restrict__ out)
{
    __shared__ __align__(16) float bias_s[4096];
    __shared__ __align__(16) float Ks[TK*DD];
    __shared__ __align__(16) float Vs[TK*DD];
    __shared__ __align__(16) float Wo_s[DD*DD], wi_s[DD*DD], wo_s[DD*DD];
    __shared__ __align__(16) float ln2_s[DD], lnf_s[DD];

    int tid = threadIdx.x;
    for (int i = tid; i < 4096; i += 128) bias_s[i] = g_bias[i];
    for (int i = tid; i < DD*DD; i += 128) { Wo_s[i] = Wo[i]; wi_s[i] = wi[i]; wo_s[i] = wo[i]; }
    if (tid < DD) { ln2_s[tid] = ln2[tid]; lnf_s[tid] = lnf[tid]; }

    int b  = blockIdx.y;
    int qi = blockIdx.x * 128 + tid;
    size_t row = (size_t)b * SS + qi;

    u64 q2[DP];
    {
        const u64* qp = (const u64*)(g_q + row * DD);
        #pragma unroll
        for (int d = 0; d < DP; d++) q2[d] = qp[d];
    }
    u64 o2[DP];
    #pragma unroll
    for (int d = 0; d < DP; d++) o2[d] = 0ull;
    float m = -INFINITY, l = 0.f;
    const float LOG2E = 1.4426950408889634f;

    const float* kbase = g_k + (size_t)b * SS * DD;
    const float* vbase = g_v + (size_t)b * SS * DD;
    __syncthreads();

    #pragma unroll 1
    for (int t = 0; t < SS / TK; t++) {
        // stage K,V tile (32 rows x 40 floats each, contiguous)
        {
            const float4* ksrc = (const float4*)(kbase + t * TK * DD);
            const float4* vsrc = (const float4*)(vbase + t * TK * DD);
            float4* kd = (float4*)Ks; float4* vd = (float4*)Vs;
            #pragma unroll
            for (int i = 0; i < 3; i++) {
                int idx = tid + i * 128;
                if (idx < TK*DD/4) { kd[idx] = ksrc[idx]; vd[idx] = vsrc[idx]; }
            }
        }
        __syncthreads();

        int boff = t * TK - qi + 2048;
        #pragma unroll 1
        for (int c = 0; c < 2; c++) {           // 2 chunks of 16 keys (I$ friendly)
            int k0 = c * 16;
            float s[16];
            #pragma unroll
            for (int kk = 0; kk < 16; kk++) {
                const u64* kr = (const u64*)(Ks + (k0 + kk) * DD);
                u64 acc = 0ull;
                #pragma unroll
                for (int d = 0; d < DP; d++) acc = ffma2(q2[d], kr[d], acc);
                float2 f = unpack2(acc);
                s[kk] = (f.x + f.y + bias_s[boff + k0 + kk]) * LOG2E;
            }
            float tmax = s[0];
            #pragma unroll
            for (int kk = 1; kk < 16; kk++) tmax = fmaxf(tmax, s[kk]);
            if (tmax > m) {                      // rare after warmup
                float corr = exp2f(m - tmax);
                l *= corr;
                u64 c2 = pack2(corr, corr);
                #pragma unroll
                for (int d = 0; d < DP; d++) o2[d] = fmul2(o2[d], c2);
                m = tmax;
            }
            #pragma unroll
            for (int kk = 0; kk < 16; kk++) {
                float p = exp2f(s[kk] - m);
                l += p;
                u64 p2 = pack2(p, p);
                const u64* vr = (const u64*)(Vs + (k0 + kk) * DD);
                #pragma unroll
                for (int d = 0; d < DP; d++) o2[d] = ffma2(p2, vr[d], o2[d]);
            }
        }
        __syncthreads();
    }

    // ---- fused epilogue (row-local) ----
    float invl = 1.0f / l;
    float oarr[DD];
    #pragma unroll
    for (int d = 0; d < DP; d++) {
        float2 f = unpack2(o2[d]);
        oarr[2*d] = f.x * invl; oarr[2*d+1] = f.y * invl;
    }
    // attn_out @ Wo
    u64 acc[DP];
    #pragma unroll
    for (int d = 0; d < DP; d++) acc[d] = 0ull;
    const u64* Wo2 = (const u64*)Wo_s;
    #pragma unroll 8
    for (int k = 0; k < DD; k++) {
        u64 ok = pack2(oarr[k], oarr[k]);
        #pragma unroll
        for (int d = 0; d < DP; d++) acc[d] = ffma2(ok, Wo2[k*DP + d], acc[d]);
    }
    // + x residual, rms(ln2)
    float x2a[DD]; float ssq = 0.f;
    {
        const u64* xp = (const u64*)(g_x + row * DD);
        #pragma unroll
        for (int d = 0; d < DP; d++) {
            float2 xv = unpack2(xp[d]); float2 ov = unpack2(acc[d]);
            float a0 = xv.x + ov.x, a1 = xv.y + ov.y;
            x2a[2*d] = a0; x2a[2*d+1] = a1;
            ssq += a0*a0 + a1*a1;
        }
    }
    float r2 = rsqrtf(ssq / 40.0f + 1e-6f);
    float h2a[DD];
    #pragma unroll
    for (int d = 0; d < DD; d++) h2a[d] = x2a[d] * r2 * ln2_s[d];
    // relu(h2 @ wi)
    u64 acc2[DP];
    #pragma unroll
    for (int d = 0; d < DP; d++) acc2[d] = 0ull;
    const u64* wi2 = (const u64*)wi_s;
    #pragma unroll 8
    for (int k = 0; k < DD; k++) {
        u64 hk = pack2(h2a[k], h2a[k]);
        #pragma unroll
        for (int d = 0; d < DP; d++) acc2[d] = ffma2(hk, wi2[k*DP + d], acc2[d]);
    }
    float f1[DD];
    #pragma unroll
    for (int d = 0; d < DP; d++) {
        float2 f = unpack2(acc2[d]);
        f1[2*d] = fmaxf(f.x, 0.f); f1[2*d+1] = fmaxf(f.y, 0.f);
    }
    // @ wo
    u64 acc3[DP];
    #pragma unroll
    for (int d = 0; d < DP; d++) acc3[d] = 0ull;
    const u64* wo2 = (const u64*)wo_s;
    #pragma unroll 8
    for (int k = 0; k < DD; k++) {
        u64 fk = pack2(f1[k], f1[k]);
        #pragma unroll
        for (int d = 0; d < DP; d++) acc3[d] = ffma2(fk, wo2[k*DP + d], acc3[d]);
    }
    // + residual, final rms(lnf), store
    float x3[DD]; float ssq3 = 0.f;
    #pragma unroll
    for (int d = 0; d < DP; d++) {
        float2 fv = unpack2(acc3[d]);
        float a0 = x2a[2*d] + fv.x, a1 = x2a[2*d+1] + fv.y;
        x3[2*d] = a0; x3[2*d+1] = a1;
        ssq3 += a0*a0 + a1*a1;
    }
    float r3 = rsqrtf(ssq3 / 40.0f + 1e-6f);
    float* orow = out + row * DD;
    #pragma unroll
    for (int d = 0; d < DP; d++) {
        *(float2*)(orow + 2*d) = make_float2(x3[2*d]   * r3 * lnf_s[2*d],
                                             x3[2*d+1] * r3 * lnf_s[2*d+1]);
    }
}

// ---------- launch ----------
extern "C" void kernel_launch(void* const* d_in, const int* in_sizes, int n_in,
                              void* d_out, int out_size) {
    const float* embs = (const float*)d_in[0];
    const float* Wa   = (const float*)d_in[1];
    const float* ba   = (const float*)d_in[2];
    const float* ln1  = (const float*)d_in[3];
    const float* Wq   = (const float*)d_in[4];
    const float* Wk   = (const float*)d_in[5];
    const float* Wv   = (const float*)d_in[6];
    const float* Wo   = (const float*)d_in[7];
    const float* ln2  = (const float*)d_in[8];
    const float* wi   = (const float*)d_in[9];
    const float* wo   = (const float*)d_in[10];
    const float* lnf  = (const float*)d_in[11];
    const float* rel_bias = (const float*)d_in[12];
    float* out = (float*)d_out;

    bias_kernel<<<16, 256>>>(rel_bias);
    kernelA<<<256, 256>>>(embs, Wa, ba, ln1, Wq, Wk, Wv);
    dim3 gridC(SS / 128, BB);
    kernelC<<<gridC, 128>>>(Wo, ln2, wi, wo, lnf, out);
}

// round 2
// speedup vs baseline: 1.4064x; 1.4064x over previous
#include <cuda_runtime.h>
#include <math.h>

typedef unsigned long long u64;

#define BB 8
#define SS 2048
#define DIN 128
#define DD 40
#define DP 20          // D/2 float2 pairs
#define NROWS (BB*SS)
#define TK 32
#define RSPLIT 4
#define KEYS_PER (SS/RSPLIT)   // 512

// ---------- scratch (device globals: no allocation allowed) ----------
__device__ float g_x[NROWS*DD];
__device__ float g_q[NROWS*DD];
__device__ float g_k[NROWS*DD];
__device__ float g_v[NROWS*DD];
__device__ float g_pm[RSPLIT*NROWS];
__device__ float g_pl[RSPLIT*NROWS];
__device__ float g_po[(size_t)RSPLIT*NROWS*DD];

// ---------- f32x2 helpers (FFMA2 only reachable via PTX) ----------
__device__ __forceinline__ u64 pack2(float x, float y) {
    u64 r; asm("mov.b64 %0,{%1,%2};" : "=l"(r) : "f"(x), "f"(y)); return r;
}
__device__ __forceinline__ float2 unpack2(u64 a) {
    float x, y; asm("mov.b64 {%0,%1},%2;" : "=f"(x), "=f"(y) : "l"(a));
    return make_float2(x, y);
}
__device__ __forceinline__ u64 ffma2(u64 a, u64 b, u64 c) {
    u64 d; asm("fma.rn.f32x2 %0,%1,%2,%3;" : "=l"(d) : "l"(a), "l"(b), "l"(c)); return d;
}
__device__ __forceinline__ u64 fmul2(u64 a, u64 b) {
    u64 d; asm("mul.rn.f32x2 %0,%1,%2;" : "=l"(d) : "l"(a), "l"(b)); return d;
}
// LDS.128 loading two packed f32x2 operands directly (no repack movs)
__device__ __forceinline__ void lds2(u64& a, u64& b, unsigned addr) {
    asm volatile("ld.shared.v2.b64 {%0,%1},[%2];" : "=l"(a), "=l"(b) : "r"(addr));
}

// bucket -> bias value, matching jax reference exactly in f32 op order
__device__ __forceinline__ int rel_bucket(int rel) {
    int bucket = (rel > 0) ? 16 : 0;
    int a = rel < 0 ? -rel : rel;
    if (a < 8) return bucket + a;
    float v = (logf((float)a * 0.125f) / 2.7725887222397811f) * 8.0f;
    int large = 8 + (int)v;
    return bucket + ((large < 15) ? large : 15);
}

// ---------- kernel A: x = relu(embs@Wa+ba); h = rms(x,ln1); q/k/v = h@W ----------
__global__ __launch_bounds__(256) void kernelA(
    const float* __restrict__ embs, const float* __restrict__ Wa,
    const float* __restrict__ ba,   const float* __restrict__ ln1,
    const float* __restrict__ Wq,   const float* __restrict__ Wk,
    const float* __restrict__ Wv)
{
    __shared__ __align__(16) float Wa_s[DIN*DD];
    __shared__ __align__(16) float Wq_s[DD*DD], Wk_s[DD*DD], Wv_s[DD*DD];
    __shared__ __align__(16) float ba_s[DD], ln1_s[DD];
    __shared__ __align__(16) float e_s[8][DIN];
    __shared__ u64 h_s[8][DD];

    int tid = threadIdx.x;
    for (int i = tid; i < DIN*DD; i += 256) Wa_s[i] = Wa[i];
    for (int i = tid; i < DD*DD; i += 256) { Wq_s[i] = Wq[i]; Wk_s[i] = Wk[i]; Wv_s[i] = Wv[i]; }
    if (tid < DD) { ba_s[tid] = ba[tid]; ln1_s[tid] = ln1[tid]; }
    __syncthreads();

    int w = tid >> 5, lane = tid & 31;
    const float2* Wa2 = (const float2*)Wa_s;
    const u64* wq2 = (const u64*)Wq_s;
    const u64* wk2 = (const u64*)Wk_s;
    const u64* wv2 = (const u64*)Wv_s;

    for (int r = 0; r < 8; r++) {
        int row = (blockIdx.x * 8 + w) * 8 + r;
        float4 ev = ((const float4*)(embs + (size_t)row * DIN))[lane];
        ((float4*)e_s[w])[lane] = ev;
        __syncwarp();

        float ax = 0.f, ay = 0.f;
        if (lane < DP) {
            ax = ba_s[2*lane]; ay = ba_s[2*lane+1];
            #pragma unroll 16
            for (int i = 0; i < DIN; i++) {
                float e = e_s[w][i];
                float2 wa = Wa2[i*DP + lane];
                ax = fmaf(e, wa.x, ax);
                ay = fmaf(e, wa.y, ay);
            }
            ax = fmaxf(ax, 0.f); ay = fmaxf(ay, 0.f);
        }
        float ssq = (lane < DP) ? (ax*ax + ay*ay) : 0.f;
        #pragma unroll
        for (int o = 16; o > 0; o >>= 1) ssq += __shfl_xor_sync(0xffffffffu, ssq, o);
        float rinv = rsqrtf(ssq / 40.0f + 1e-6f);

        if (lane < DP) {
            float hx = ax * rinv * ln1_s[2*lane];
            float hy = ay * rinv * ln1_s[2*lane+1];
            *(float2*)(g_x + (size_t)row*DD + 2*lane) = make_float2(ax, ay);
            h_s[w][2*lane]   = pack2(hx, hx);
            h_s[w][2*lane+1] = pack2(hy, hy);
        }
        __syncwarp();

        if (lane < DP) {
            u64 aq = 0, ak = 0, av = 0;
            #pragma unroll 8
            for (int i = 0; i < DD; i++) {
                u64 h2 = h_s[w][i];
                aq = ffma2(h2, wq2[i*DP + lane], aq);
                ak = ffma2(h2, wk2[i*DP + lane], ak);
                av = ffma2(h2, wv2[i*DP + lane], av);
            }
            float2 fq = unpack2(aq), fk = unpack2(ak), fv = unpack2(av);
            *(float2*)(g_q + (size_t)row*DD + 2*lane) = fq;
            *(float2*)(g_k + (size_t)row*DD + 2*lane) = fk;
            *(float2*)(g_v + (size_t)row*DD + 2*lane) = fv;
        }
        __syncwarp();
    }
}

// ---------- attention main loop: split-K x4, flash softmax, partial out ----------
// grid (16, 8, 4): x = q-tile(128), y = batch, z = key-split.
__global__ __launch_bounds__(128, 4) void attn_kernel(const float* __restrict__ rel_bias)
{
    __shared__ __align__(16) float bias_s[KEYS_PER + 128];
    __shared__ __align__(16) float Ks[TK*DD];
    __shared__ __align__(16) float Vs[TK*DD];

    int tid = threadIdx.x;
    int b = blockIdx.y, z = blockIdx.z;
    int q0 = blockIdx.x * 128;
    int qi = q0 + tid;
    size_t row = (size_t)b * SS + qi;

    // per-CTA bias window: entry i covers rel = z*512 - q0 - 127 + i
    int rel0 = z * KEYS_PER - q0 - 127;
    for (int i = tid; i < KEYS_PER + 128; i += 128)
        bias_s[i] = rel_bias[rel_bucket(rel0 + i)];

    u64 q2[DP];
    {
        const u64* qp = (const u64*)(g_q + row * DD);
        #pragma unroll
        for (int d = 0; d < DP; d++) q2[d] = qp[d];
    }
    u64 o2[DP];
    #pragma unroll
    for (int d = 0; d < DP; d++) o2[d] = 0ull;
    float m = -INFINITY, l = 0.f;
    const float LOG2E = 1.4426950408889634f;

    const float* kbase = g_k + ((size_t)b * SS + z * KEYS_PER) * DD;
    const float* vbase = g_v + ((size_t)b * SS + z * KEYS_PER) * DD;
    unsigned ks_base = (unsigned)__cvta_generic_to_shared(Ks);
    unsigned vs_base = (unsigned)__cvta_generic_to_shared(Vs);
    int base_off = 127 - tid;
    __syncthreads();

    #pragma unroll 1
    for (int t = 0; t < KEYS_PER / TK; t++) {
        {
            const float4* ksrc = (const float4*)(kbase + t * TK * DD);
            const float4* vsrc = (const float4*)(vbase + t * TK * DD);
            float4* kd = (float4*)Ks; float4* vd = (float4*)Vs;
            #pragma unroll
            for (int i = 0; i < 3; i++) {
                int idx = tid + i * 128;
                if (idx < TK*DD/4) { kd[idx] = ksrc[idx]; vd[idx] = vsrc[idx]; }
            }
        }
        __syncthreads();

        int boff = t * TK + base_off;
        #pragma unroll 1
        for (int c = 0; c < 2; c++) {
            int k0 = c * 16;
            float s[16];
            #pragma unroll
            for (int kk = 0; kk < 16; kk++) {
                unsigned ka = ks_base + (k0 + kk) * (DD*4);
                u64 a0 = 0, a1 = 0;
                #pragma unroll
                for (int d = 0; d < 10; d++) {
                    u64 ua, ub;
                    lds2(ua, ub, ka + d * 16);
                    a0 = ffma2(q2[2*d],   ua, a0);
                    a1 = ffma2(q2[2*d+1], ub, a1);
                }
                float2 f0 = unpack2(a0), f1 = unpack2(a1);
                s[kk] = (f0.x + f0.y + f1.x + f1.y + bias_s[boff + k0 + kk]) * LOG2E;
            }
            float tmax = s[0];
            #pragma unroll
            for (int kk = 1; kk < 16; kk++) tmax = fmaxf(tmax, s[kk]);
            if (tmax > m) {
                float corr = exp2f(m - tmax);
                l *= corr;
                u64 c2 = pack2(corr, corr);
                #pragma unroll
                for (int d = 0; d < DP; d++) o2[d] = fmul2(o2[d], c2);
                m = tmax;
            }
            #pragma unroll
            for (int kk = 0; kk < 16; kk++) {
                float p = exp2f(s[kk] - m);
                l += p;
                u64 p2 = pack2(p, p);
                unsigned va = vs_base + (k0 + kk) * (DD*4);
                #pragma unroll
                for (int d = 0; d < 10; d++) {
                    u64 ua, ub;
                    lds2(ua, ub, va + d * 16);
                    o2[2*d]   = ffma2(p2, ua, o2[2*d]);
                    o2[2*d+1] = ffma2(p2, ub, o2[2*d+1]);
                }
            }
            __syncwarp();
        }
        __syncthreads();
    }

    // write partials (unnormalized o, running m in log2 domain, l)
    size_t pidx = (size_t)z * NROWS + row;
    g_pm[pidx] = m;
    g_pl[pidx] = l;
    float2* pop = (float2*)(g_po + pidx * DD);
    #pragma unroll
    for (int d = 0; d < DP; d++) pop[d] = unpack2(o2[d]);
}

// ---------- combine partials + fused epilogue ----------
__global__ __launch_bounds__(128) void combine_kernel(
    const float* __restrict__ Wo, const float* __restrict__ ln2,
    const float* __restrict__ wi, const float* __restrict__ wo,
    const float* __restrict__ lnf, float* __restrict__ out)
{
    __shared__ __align__(16) float Wo_s[DD*DD], wi_s[DD*DD], wo_s[DD*DD];
    __shared__ __align__(16) float ln2_s[DD], lnf_s[DD];
    int tid = threadIdx.x;
    for (int i = tid; i < DD*DD; i += 128) { Wo_s[i] = Wo[i]; wi_s[i] = wi[i]; wo_s[i] = wo[i]; }
    if (tid < DD) { ln2_s[tid] = ln2[tid]; lnf_s[tid] = lnf[tid]; }
    __syncthreads();

    size_t row = (size_t)blockIdx.x * 128 + tid;

    float mz[RSPLIT], lz[RSPLIT];
    float M = -INFINITY;
    #pragma unroll
    for (int z = 0; z < RSPLIT; z++) {
        mz[z] = g_pm[(size_t)z * NROWS + row];
        lz[z] = g_pl[(size_t)z * NROWS + row];
        M = fmaxf(M, mz[z]);
    }
    float L = 0.f;
    float oarr[DD];
    #pragma unroll
    for (int d = 0; d < DD; d++) oarr[d] = 0.f;
    #pragma unroll
    for (int z = 0; z < RSPLIT; z++) {
        float wz = exp2f(mz[z] - M);
        L = fmaf(wz, lz[z], L);
        const float4* pp = (const float4*)(g_po + ((size_t)z * NROWS + row) * DD);
        #pragma unroll
        for (int d = 0; d < 10; d++) {
            float4 v = pp[d];
            oarr[4*d]   = fmaf(wz, v.x, oarr[4*d]);
            oarr[4*d+1] = fmaf(wz, v.y, oarr[4*d+1]);
            oarr[4*d+2] = fmaf(wz, v.z, oarr[4*d+2]);
            oarr[4*d+3] = fmaf(wz, v.w, oarr[4*d+3]);
        }
    }
    float invl = 1.0f / L;
    #pragma unroll
    for (int d = 0; d < DD; d++) oarr[d] *= invl;

    // attn_out @ Wo
    u64 acc[DP];
    #pragma unroll
    for (int d = 0; d < DP; d++) acc[d] = 0ull;
    const u64* Wo2 = (const u64*)Wo_s;
    #pragma unroll 8
    for (int k = 0; k < DD; k++) {
        u64 ok = pack2(oarr[k], oarr[k]);
        #pragma unroll
        for (int d = 0; d < DP; d++) acc[d] = ffma2(ok, Wo2[k*DP + d], acc[d]);
    }
    // + x residual, rms(ln2)
    float x2a[DD]; float ssq = 0.f;
    {
        const u64* xp = (const u64*)(g_x + row * DD);
        #pragma unroll
        for (int d = 0; d < DP; d++) {
            float2 xv = unpack2(xp[d]); float2 ov = unpack2(acc[d]);
            float a0 = xv.x + ov.x, a1 = xv.y + ov.y;
            x2a[2*d] = a0; x2a[2*d+1] = a1;
            ssq += a0*a0 + a1*a1;
        }
    }
    float r2 = rsqrtf(ssq / 40.0f + 1e-6f);
    float h2a[DD];
    #pragma unroll
    for (int d = 0; d < DD; d++) h2a[d] = x2a[d] * r2 * ln2_s[d];
    // relu(h2 @ wi)
    u64 acc2[DP];
    #pragma unroll
    for (int d = 0; d < DP; d++) acc2[d] = 0ull;
    const u64* wi2 = (const u64*)wi_s;
    #pragma unroll 8
    for (int k = 0; k < DD; k++) {
        u64 hk = pack2(h2a[k], h2a[k]);
        #pragma unroll
        for (int d = 0; d < DP; d++) acc2[d] = ffma2(hk, wi2[k*DP + d], acc2[d]);
    }
    float f1[DD];
    #pragma unroll
    for (int d = 0; d < DP; d++) {
        float2 f = unpack2(acc2[d]);
        f1[2*d] = fmaxf(f.x, 0.f); f1[2*d+1] = fmaxf(f.y, 0.f);
    }
    // @ wo
    u64 acc3[DP];
    #pragma unroll
    for (int d = 0; d < DP; d++) acc3[d] = 0ull;
    const u64* wo2 = (const u64*)wo_s;
    #pragma unroll 8
    for (int k = 0; k < DD; k++) {
        u64 fk = pack2(f1[k], f1[k]);
        #pragma unroll
        for (int d = 0; d < DP; d++) acc3[d] = ffma2(fk, wo2[k*DP + d], acc3[d]);
    }
    // + residual, final rms(lnf), store
    float x3[DD]; float ssq3 = 0.f;
    #pragma unroll
    for (int d = 0; d < DP; d++) {
        float2 fv = unpack2(acc3[d]);
        float a0 = x2a[2*d] + fv.x, a1 = x2a[2*d+1] + fv.y;
        x3[2*d] = a0; x3[2*d+1] = a1;
        ssq3 += a0*a0 + a1*a1;
    }
    float r3 = rsqrtf(ssq3 / 40.0f + 1e-6f);
    float* orow = out + row * DD;
    #pragma unroll
    for (int d = 0; d < DP; d++) {
        *(float2*)(orow + 2*d) = make_float2(x3[2*d]   * r3 * lnf_s[2*d],
                                             x3[2*d+1] * r3 * lnf_s[2*d+1]);
    }
}

// ---------- launch ----------
extern "C" void kernel_launch(void* const* d_in, const int* in_sizes, int n_in,
                              void* d_out, int out_size) {
    const float* embs = (const float*)d_in[0];
    const float* Wa   = (const float*)d_in[1];
    const float* ba   = (const float*)d_in[2];
    const float* ln1  = (const float*)d_in[3];
    const float* Wq   = (const float*)d_in[4];
    const float* Wk   = (const float*)d_in[5];
    const float* Wv   = (const float*)d_in[6];
    const float* Wo   = (const float*)d_in[7];
    const float* ln2  = (const float*)d_in[8];
    const float* wi   = (const float*)d_in[9];
    const float* wo   = (const float*)d_in[10];
    const float* lnf  = (const float*)d_in[11];
    const float* rel_bias = (const float*)d_in[12];
    float* out = (float*)d_out;

    kernelA<<<256, 256>>>(embs, Wa, ba, ln1, Wq, Wk, Wv);
    dim3 gridB(SS / 128, BB, RSPLIT);
    attn_kernel<<<gridB, 128>>>(rel_bias);
    combine_kernel<<<NROWS / 128, 128>>>(Wo, ln2, wi, wo, lnf, out);
}

// round 3
// speedup vs baseline: 1.4296x; 1.0165x over previous
#include <cuda_runtime.h>
#include <math.h>

typedef unsigned long long u64;

#define BB 8
#define SS 2048
#define DIN 128
#define DD 40
#define DP 20
#define NROWS (BB*SS)
#define RSPLIT 8
#define KEYS_PER (SS/RSPLIT)   // 256
#define TKA 64                 // keys per smem tile in attn

// ---------- scratch (device globals: no allocation allowed) ----------
__device__ float g_x[NROWS*DD];
__device__ float g_q[NROWS*DD];
__device__ float g_k[NROWS*DD];
__device__ float g_v[NROWS*DD];
__device__ float g_pm[RSPLIT*NROWS];
__device__ float g_pl[RSPLIT*NROWS];
__device__ float g_po[(size_t)RSPLIT*NROWS*DD];

// ---------- f32x2 helpers ----------
__device__ __forceinline__ u64 pack2(float x, float y) {
    u64 r; asm("mov.b64 %0,{%1,%2};" : "=l"(r) : "f"(x), "f"(y)); return r;
}
__device__ __forceinline__ float2 unpack2(u64 a) {
    float x, y; asm("mov.b64 {%0,%1},%2;" : "=f"(x), "=f"(y) : "l"(a));
    return make_float2(x, y);
}
__device__ __forceinline__ u64 ffma2(u64 a, u64 b, u64 c) {
    u64 d; asm("fma.rn.f32x2 %0,%1,%2,%3;" : "=l"(d) : "l"(a), "l"(b), "l"(c)); return d;
}
__device__ __forceinline__ u64 fmul2(u64 a, u64 b) {
    u64 d; asm("mul.rn.f32x2 %0,%1,%2;" : "=l"(d) : "l"(a), "l"(b)); return d;
}
__device__ __forceinline__ u64 fadd2(u64 a, u64 b) {
    u64 d; asm("add.rn.f32x2 %0,%1,%2;" : "=l"(d) : "l"(a), "l"(b)); return d;
}
// LDS.128 -> two packed f32x2 operands (non-volatile: let ptxas schedule)
__device__ __forceinline__ void lds2(u64& a, u64& b, unsigned addr) {
    asm("ld.shared.v2.b64 {%0,%1},[%2];" : "=l"(a), "=l"(b) : "r"(addr));
}

// bucket mapping, f32 op order matches jax reference
__device__ __forceinline__ int rel_bucket(int rel) {
    int bucket = (rel > 0) ? 16 : 0;
    int a = rel < 0 ? -rel : rel;
    if (a < 8) return bucket + a;
    float v = (logf((float)a * 0.125f) / 2.7725887222397811f) * 8.0f;
    int large = 8 + (int)v;
    return bucket + ((large < 15) ? large : 15);
}

// ---------- kernel A: thread-per-row adapter+rms+QKV ----------
// grid 256 x 64 threads: row = blockIdx.x*64 + tid
__device__ __forceinline__ void qkv_pass(const float* h40, unsigned wsm, float* gout) {
    u64 acc[DP];
    #pragma unroll
    for (int p = 0; p < DP; p++) acc[p] = 0ull;
    #pragma unroll 4
    for (int k = 0; k < DD; k++) {
        u64 hk = pack2(h40[k], h40[k]);
        unsigned base = wsm + k * (DD*4);
        #pragma unroll
        for (int p = 0; p < 10; p++) {
            u64 ua, ub;
            lds2(ua, ub, base + p * 16);
            acc[2*p]   = ffma2(hk, ua, acc[2*p]);
            acc[2*p+1] = ffma2(hk, ub, acc[2*p+1]);
        }
    }
    #pragma unroll
    for (int p = 0; p < DP; p++) {
        float2 f = unpack2(acc[p]);
        *(float2*)(gout + 2*p) = f;
    }
}

__global__ __launch_bounds__(64) void kernelA(
    const float* __restrict__ embs, const float* __restrict__ Wa,
    const float* __restrict__ ba,   const float* __restrict__ ln1,
    const float* __restrict__ Wq,   const float* __restrict__ Wk,
    const float* __restrict__ Wv)
{
    __shared__ __align__(16) float Wa_s[DIN*DD];
    __shared__ __align__(16) float Wq_s[DD*DD], Wk_s[DD*DD], Wv_s[DD*DD];
    __shared__ __align__(16) float ba_s[DD], ln1_s[DD];

    int tid = threadIdx.x;
    for (int i = tid; i < DIN*DD/4; i += 64) ((float4*)Wa_s)[i] = ((const float4*)Wa)[i];
    for (int i = tid; i < DD*DD/4; i += 64) {
        ((float4*)Wq_s)[i] = ((const float4*)Wq)[i];
        ((float4*)Wk_s)[i] = ((const float4*)Wk)[i];
        ((float4*)Wv_s)[i] = ((const float4*)Wv)[i];
    }
    if (tid < DD) { ba_s[tid] = ba[tid]; ln1_s[tid] = ln1[tid]; }
    __syncthreads();

    size_t row = (size_t)blockIdx.x * 64 + tid;
    const float4* erow = (const float4*)(embs + row * DIN);
    unsigned wa = (unsigned)__cvta_generic_to_shared(Wa_s);

    u64 acc[DP];
    #pragma unroll
    for (int p = 0; p < DP; p++) acc[p] = pack2(ba_s[2*p], ba_s[2*p+1]);

    #pragma unroll 4
    for (int c = 0; c < DIN/4; c++) {
        float4 e = erow[c];
        float ej[4] = {e.x, e.y, e.z, e.w};
        #pragma unroll
        for (int j = 0; j < 4; j++) {
            u64 ee = pack2(ej[j], ej[j]);
            unsigned base = wa + (4*c + j) * (DD*4);
            #pragma unroll
            for (int p = 0; p < 10; p++) {
                u64 ua, ub;
                lds2(ua, ub, base + p * 16);
                acc[2*p]   = ffma2(ee, ua, acc[2*p]);
                acc[2*p+1] = ffma2(ee, ub, acc[2*p+1]);
            }
        }
    }

    // relu, store x, rms
    float h40[DD];
    float ssq = 0.f;
    float* xrow = g_x + row * DD;
    #pragma unroll
    for (int p = 0; p < DP; p++) {
        float2 f = unpack2(acc[p]);
        float x0 = fmaxf(f.x, 0.f), x1 = fmaxf(f.y, 0.f);
        *(float2*)(xrow + 2*p) = make_float2(x0, x1);
        ssq += x0*x0 + x1*x1;
        h40[2*p] = x0; h40[2*p+1] = x1;
    }
    float rinv = rsqrtf(ssq / 40.0f + 1e-6f);
    #pragma unroll
    for (int k = 0; k < DD; k++) h40[k] = h40[k] * rinv * ln1_s[k];

    qkv_pass(h40, (unsigned)__cvta_generic_to_shared(Wq_s), g_q + row * DD);
    qkv_pass(h40, (unsigned)__cvta_generic_to_shared(Wk_s), g_k + row * DD);
    qkv_pass(h40, (unsigned)__cvta_generic_to_shared(Wv_s), g_v + row * DD);
}

// ---------- attention: d-split flash, split-K x8 ----------
// grid (16, 8, 8), 256 threads: 128 queries x 2 half-dims.
__global__ __launch_bounds__(256, 3) void attn_kernel(const float* __restrict__ rel_bias)
{
    __shared__ __align__(16) float bias_s[KEYS_PER + 128];
    __shared__ __align__(16) float Ks[TKA*DD];
    __shared__ __align__(16) float Vs[TKA*DD];

    int tid = threadIdx.x;
    int warp = tid >> 5, lane = tid & 31;
    int half = lane >> 4;
    int qlocal = warp * 16 + (lane & 15);
    int b = blockIdx.y, z = blockIdx.z;
    int q0 = blockIdx.x * 128;
    int qi = q0 + qlocal;
    size_t row = (size_t)b * SS + qi;
    const float LOG2E = 1.4426950408889634f;

    int rel0 = z * KEYS_PER - q0 - 127;
    for (int i = tid; i < KEYS_PER + 128; i += 256)
        bias_s[i] = rel_bias[rel_bucket(rel0 + i)] * LOG2E;

    u64 q2[10];
    {
        const u64* qp = (const u64*)(g_q + row * DD) + half * 10;
        #pragma unroll
        for (int d = 0; d < 10; d++) q2[d] = qp[d];
    }
    u64 o2[10];
    #pragma unroll
    for (int d = 0; d < 10; d++) o2[d] = 0ull;
    float m = -INFINITY, l = 0.f;

    const float* kbase = g_k + ((size_t)b * SS + z * KEYS_PER) * DD;
    const float* vbase = g_v + ((size_t)b * SS + z * KEYS_PER) * DD;
    unsigned ks_base = (unsigned)__cvta_generic_to_shared(Ks);
    unsigned vs_base = (unsigned)__cvta_generic_to_shared(Vs);
    int base_off = 127 - qlocal;
    unsigned hoff = half * 80;
    __syncthreads();

    #pragma unroll 1
    for (int t = 0; t < KEYS_PER / TKA; t++) {
        {
            const float4* ksrc = (const float4*)(kbase + t * TKA * DD);
            const float4* vsrc = (const float4*)(vbase + t * TKA * DD);
            float4* kd = (float4*)Ks; float4* vd = (float4*)Vs;
            #pragma unroll
            for (int i = tid; i < TKA*DD/4; i += 256) { kd[i] = ksrc[i]; vd[i] = vsrc[i]; }
        }
        __syncthreads();

        int boff = t * TKA + base_off;
        #pragma unroll 1
        for (int c = 0; c < TKA/8; c++) {
            int k0 = c * 8;
            float s[8];
            #pragma unroll
            for (int kk = 0; kk < 8; kk++) {
                unsigned ka = ks_base + (k0 + kk) * (DD*4) + hoff;
                u64 a0 = 0, a1 = 0;
                #pragma unroll
                for (int d = 0; d < 5; d++) {
                    u64 ua, ub;
                    lds2(ua, ub, ka + d * 16);
                    a0 = ffma2(q2[2*d],   ua, a0);
                    a1 = ffma2(q2[2*d+1], ub, a1);
                }
                float2 f = unpack2(fadd2(a0, a1));
                float dpart = f.x + f.y;
                float dfull = dpart + __shfl_xor_sync(0xffffffffu, dpart, 16);
                s[kk] = fmaf(dfull, LOG2E, bias_s[boff + k0 + kk]);
            }
            float tmax = s[0];
            #pragma unroll
            for (int kk = 1; kk < 8; kk++) tmax = fmaxf(tmax, s[kk]);
            if (tmax > m) {
                float corr = exp2f(m - tmax);
                l *= corr;
                u64 c2 = pack2(corr, corr);
                #pragma unroll
                for (int d = 0; d < 10; d++) o2[d] = fmul2(o2[d], c2);
                m = tmax;
            }
            #pragma unroll
            for (int kk = 0; kk < 8; kk++) {
                float p = exp2f(s[kk] - m);
                l += p;
                u64 p2 = pack2(p, p);
                unsigned va = vs_base + (k0 + kk) * (DD*4) + hoff;
                #pragma unroll
                for (int d = 0; d < 5; d++) {
                    u64 ua, ub;
                    lds2(ua, ub, va + d * 16);
                    o2[2*d]   = ffma2(p2, ua, o2[2*d]);
                    o2[2*d+1] = ffma2(p2, ub, o2[2*d+1]);
                }
            }
        }
        __syncthreads();
    }

    size_t pidx = (size_t)z * NROWS + row;
    if (half == 0) { g_pm[pidx] = m; g_pl[pidx] = l; }
    float* pop = g_po + pidx * DD + half * 20;
    #pragma unroll
    for (int d = 0; d < 10; d++) *(float2*)(pop + 2*d) = unpack2(o2[d]);
}

// ---------- combine partials + fused epilogue ----------
__global__ __launch_bounds__(128) void combine_kernel(
    const float* __restrict__ Wo, const float* __restrict__ ln2,
    const float* __restrict__ wi, const float* __restrict__ wo,
    const float* __restrict__ lnf, float* __restrict__ out)
{
    __shared__ __align__(16) float Wo_s[DD*DD], wi_s[DD*DD], wo_s[DD*DD];
    __shared__ __align__(16) float ln2_s[DD], lnf_s[DD];
    int tid = threadIdx.x;
    for (int i = tid; i < DD*DD; i += 128) { Wo_s[i] = Wo[i]; wi_s[i] = wi[i]; wo_s[i] = wo[i]; }
    if (tid < DD) { ln2_s[tid] = ln2[tid]; lnf_s[tid] = lnf[tid]; }
    __syncthreads();

    size_t row = (size_t)blockIdx.x * 128 + tid;

    float M = -INFINITY;
    float mz[RSPLIT], lz[RSPLIT];
    #pragma unroll
    for (int z = 0; z < RSPLIT; z++) {
        mz[z] = g_pm[(size_t)z * NROWS + row];
        lz[z] = g_pl[(size_t)z * NROWS + row];
        M = fmaxf(M, mz[z]);
    }
    float L = 0.f;
    float oarr[DD];
    #pragma unroll
    for (int d = 0; d < DD; d++) oarr[d] = 0.f;
    #pragma unroll
    for (int z = 0; z < RSPLIT; z++) {
        float wz = exp2f(mz[z] - M);
        L = fmaf(wz, lz[z], L);
        const float4* pp = (const float4*)(g_po + ((size_t)z * NROWS + row) * DD);
        #pragma unroll
        for (int d = 0; d < 10; d++) {
            float4 v = pp[d];
            oarr[4*d]   = fmaf(wz, v.x, oarr[4*d]);
            oarr[4*d+1] = fmaf(wz, v.y, oarr[4*d+1]);
            oarr[4*d+2] = fmaf(wz, v.z, oarr[4*d+2]);
            oarr[4*d+3] = fmaf(wz, v.w, oarr[4*d+3]);
        }
    }
    float invl = 1.0f / L;
    #pragma unroll
    for (int d = 0; d < DD; d++) oarr[d] *= invl;

    // attn_out @ Wo
    u64 acc[DP];
    #pragma unroll
    for (int d = 0; d < DP; d++) acc[d] = 0ull;
    const u64* Wo2 = (const u64*)Wo_s;
    #pragma unroll 8
    for (int k = 0; k < DD; k++) {
        u64 ok = pack2(oarr[k], oarr[k]);
        #pragma unroll
        for (int d = 0; d < DP; d++) acc[d] = ffma2(ok, Wo2[k*DP + d], acc[d]);
    }
    // + x residual, rms(ln2)
    float x2a[DD]; float ssq = 0.f;
    {
        const u64* xp = (const u64*)(g_x + row * DD);
        #pragma unroll
        for (int d = 0; d < DP; d++) {
            float2 xv = unpack2(xp[d]); float2 ov = unpack2(acc[d]);
            float a0 = xv.x + ov.x, a1 = xv.y + ov.y;
            x2a[2*d] = a0; x2a[2*d+1] = a1;
            ssq += a0*a0 + a1*a1;
        }
    }
    float r2 = rsqrtf(ssq / 40.0f + 1e-6f);
    float h2a[DD];
    #pragma unroll
    for (int d = 0; d < DD; d++) h2a[d] = x2a[d] * r2 * ln2_s[d];
    // relu(h2 @ wi)
    u64 acc2[DP];
    #pragma unroll
    for (int d = 0; d < DP; d++) acc2[d] = 0ull;
    const u64* wi2 = (const u64*)wi_s;
    #pragma unroll 8
    for (int k = 0; k < DD; k++) {
        u64 hk = pack2(h2a[k], h2a[k]);
        #pragma unroll
        for (int d = 0; d < DP; d++) acc2[d] = ffma2(hk, wi2[k*DP + d], acc2[d]);
    }
    float f1[DD];
    #pragma unroll
    for (int d = 0; d < DP; d++) {
        float2 f = unpack2(acc2[d]);
        f1[2*d] = fmaxf(f.x, 0.f); f1[2*d+1] = fmaxf(f.y, 0.f);
    }
    // @ wo
    u64 acc3[DP];
    #pragma unroll
    for (int d = 0; d < DP; d++) acc3[d] = 0ull;
    const u64* wo2 = (const u64*)wo_s;
    #pragma unroll 8
    for (int k = 0; k < DD; k++) {
        u64 fk = pack2(f1[k], f1[k]);
        #pragma unroll
        for (int d = 0; d < DP; d++) acc3[d] = ffma2(fk, wo2[k*DP + d], acc3[d]);
    }
    // + residual, final rms(lnf), store
    float x3[DD]; float ssq3 = 0.f;
    #pragma unroll
    for (int d = 0; d < DP; d++) {
        float2 fv = unpack2(acc3[d]);
        float a0 = x2a[2*d] + fv.x, a1 = x2a[2*d+1] + fv.y;
        x3[2*d] = a0; x3[2*d+1] = a1;
        ssq3 += a0*a0 + a1*a1;
    }
    float r3 = rsqrtf(ssq3 / 40.0f + 1e-6f);
    float* orow = out + row * DD;
    #pragma unroll
    for (int d = 0; d < DP; d++) {
        *(float2*)(orow + 2*d) = make_float2(x3[2*d]   * r3 * lnf_s[2*d],
                                             x3[2*d+1] * r3 * lnf_s[2*d+1]);
    }
}

// ---------- launch ----------
extern "C" void kernel_launch(void* const* d_in, const int* in_sizes, int n_in,
                              void* d_out, int out_size) {
    const float* embs = (const float*)d_in[0];
    const float* Wa   = (const float*)d_in[1];
    const float* ba   = (const float*)d_in[2];
    const float* ln1  = (const float*)d_in[3];
    const float* Wq   = (const float*)d_in[4];
    const float* Wk   = (const float*)d_in[5];
    const float* Wv   = (const float*)d_in[6];
    const float* Wo   = (const float*)d_in[7];
    const float* ln2  = (const float*)d_in[8];
    const float* wi   = (const float*)d_in[9];
    const float* wo   = (const float*)d_in[10];
    const float* lnf  = (const float*)d_in[11];
    const float* rel_bias = (const float*)d_in[12];
    float* out = (float*)d_out;

    kernelA<<<NROWS/64, 64>>>(embs, Wa, ba, ln1, Wq, Wk, Wv);
    dim3 gridB(SS / 128, BB, RSPLIT);
    attn_kernel<<<gridB, 256>>>(rel_bias);
    combine_kernel<<<NROWS/128, 128>>>(Wo, ln2, wi, wo, lnf, out);
}